// round 16
// baseline (speedup 1.0000x reference)
#include <cuda_runtime.h>
#include <cuda_fp16.h>
#include <math.h>
#include <stdint.h>

#define NTOK 16384
#define CDIM 8192
#define HDIM 2048
#define IDIM 8192

// ---------------------------------------------------------------------------
// Scratch (__device__ globals; allocation-free rule)
// ---------------------------------------------------------------------------
__device__ __align__(256) __half g_xh[(size_t)CDIM * HDIM];    // gathered x, fp16
__device__ __align__(256) __half g_wgh[(size_t)IDIM * HDIM];
__device__ __align__(256) __half g_wuh[(size_t)IDIM * HDIM];
__device__ __align__(256) __half g_wdh[(size_t)HDIM * IDIM];
__device__ __align__(256) __half g_hh[(size_t)CDIM * IDIM];    // silu(g)*u fp16
__device__ __align__(256) float  g_down[(size_t)CDIM * HDIM];

// ---------------------------------------------------------------------------
// helpers (plain sm_80-era PTX only)
// ---------------------------------------------------------------------------
__device__ __forceinline__ uint32_t smem_u32(const void* p) {
    return (uint32_t)__cvta_generic_to_shared(p);
}
__device__ __forceinline__ void ldsm4(uint32_t a, uint32_t* r) {
    asm volatile("ldmatrix.sync.aligned.m8n8.x4.shared.b16 {%0,%1,%2,%3}, [%4];"
                 : "=r"(r[0]), "=r"(r[1]), "=r"(r[2]), "=r"(r[3]) : "r"(a));
}
__device__ __forceinline__ void hmma(float* c, const uint32_t* a,
                                     uint32_t b0, uint32_t b1) {
    asm volatile(
        "mma.sync.aligned.m16n8k16.row.col.f32.f16.f16.f32 "
        "{%0,%1,%2,%3},{%4,%5,%6,%7},{%8,%9},{%0,%1,%2,%3};"
        : "+f"(c[0]), "+f"(c[1]), "+f"(c[2]), "+f"(c[3])
        : "r"(a[0]), "r"(a[1]), "r"(a[2]), "r"(a[3]), "r"(b0), "r"(b1));
}
#define CP16(dst, src) \
    asm volatile("cp.async.cg.shared.global [%0], [%1], 16;" \
                 :: "r"(dst), "l"(src))
#define CP_COMMIT() asm volatile("cp.async.commit_group;")
#define CP_WAIT1()  asm volatile("cp.async.wait_group 1;")
#define CP_WAIT0()  asm volatile("cp.async.wait_group 0;")

__device__ __forceinline__ uint2 cvt4h(float4 v) {
    __half2 a = __floats2half2_rn(v.x, v.y);
    __half2 b = __floats2half2_rn(v.z, v.w);
    return make_uint2(*reinterpret_cast<uint32_t*>(&a),
                      *reinterpret_cast<uint32_t*>(&b));
}
__device__ __forceinline__ float silu(float g) { return g / (1.f + __expf(-g)); }

// smem rows: 32 fp16 padded to 40 (80B = 5x16B) — conflict-free ldmatrix
#define ROWB 80
// k1 planes: A(128r) | G(128r) | U(128r); 3 stages
#define K1_G     10240
#define K1_U     20480
#define STAGE1   30720
#define SMEM1    (3 * STAGE1)   // 90 KB
// k2 planes: A(256r) | B(128r); 3 stages
#define K2_B     20480
#define STAGE2   30720
#define SMEM2    (3 * STAGE2)   // 90 KB

#define NC1 (HDIM / 32)   // 64 chunks
#define NC2 (IDIM / 32)   // 256 chunks

// ---------------------------------------------------------------------------
// pre-passes: fp32 -> fp16 (weights; gathered x)
// ---------------------------------------------------------------------------
__global__ __launch_bounds__(256)
void conv_h(const float4* __restrict__ W, __half* __restrict__ out, int n8)
{
    for (int i = blockIdx.x * 256 + threadIdx.x; i < n8; i += gridDim.x * 256) {
        float4 v0 = W[2 * i];
        float4 v1 = W[2 * i + 1];
        uint2 h0 = cvt4h(v0);
        uint2 h1 = cvt4h(v1);
        *reinterpret_cast<uint4*>(out + 8 * (size_t)i) =
            make_uint4(h0.x, h0.y, h1.x, h1.y);
    }
}
__global__ __launch_bounds__(256)
void conv_gather_h(const float* __restrict__ x, const int* __restrict__ fg)
{
    const int c = blockIdx.x;
    const float4* src = reinterpret_cast<const float4*>(
        x + (size_t)__ldg(fg + c) * HDIM);
    const size_t o = (size_t)c * HDIM;
#pragma unroll
    for (int i = threadIdx.x; i < HDIM / 4; i += 256)
        *reinterpret_cast<uint2*>(g_xh + o + 4 * i) = cvt4h(src[i]);
}

// ---------------------------------------------------------------------------
// Kernel 1: dual GEMM (gate,up) + SiLU. CTA 128m x 128n (both mats).
// 8 warps of 64x64: warps 0-3 gate (2m x 2n), warps 4-7 up.
// cp.async 3-stage pipeline; pure fp16 MMA.
// ---------------------------------------------------------------------------
__global__ __launch_bounds__(256, 1)
void k1_gateup()
{
    extern __shared__ __align__(128) char sm[];
    const uint32_t smb = smem_u32(sm);
    const int tid  = threadIdx.x;
    const int wid  = tid >> 5;
    const int lane = tid & 31;
    const int m0 = blockIdx.x * 128;   // m fastest -> B tiles L2-resident
    const int n0 = blockIdx.y * 128;

    // cp.async geometry: 2 threads/row (128 rows), 2x16B per plane per thread
    const int prow = tid >> 1;
    const int ph   = tid & 1;
    const size_t aOff = (size_t)(m0 + prow) * HDIM + ph * 16;
    const size_t bOff = (size_t)(n0 + prow) * HDIM + ph * 16;
    const uint32_t st0 = (uint32_t)(prow * ROWB + ph * 32);

#define K1_ISSUE(SB, K0) do {                                                  \
    CP16((SB) + st0,               g_xh  + aOff + (K0));                       \
    CP16((SB) + st0 + 16,          g_xh  + aOff + (K0) + 8);                   \
    CP16((SB) + K1_G + st0,        g_wgh + bOff + (K0));                       \
    CP16((SB) + K1_G + st0 + 16,   g_wgh + bOff + (K0) + 8);                   \
    CP16((SB) + K1_U + st0,        g_wuh + bOff + (K0));                       \
    CP16((SB) + K1_U + st0 + 16,   g_wuh + bOff + (K0) + 8);                   \
    CP_COMMIT();                                                               \
} while (0)

    // ldmatrix lane geometry; warp tile 64x64
    const int laneRow = ((lane >> 3) & 1) * 8 + (lane & 7);
    const int laneK   = (lane >> 4) * 16;
    const int wg  = wid & 3;
    const int R   = 64 * (wg >> 1);
    const int Cw  = 64 * (wg & 1);
    const int bSec = (wid >= 4) ? K1_U : K1_G;

    float acc[4][8][4];
#pragma unroll
    for (int f = 0; f < 4; f++)
#pragma unroll
        for (int n = 0; n < 8; n++)
#pragma unroll
            for (int q = 0; q < 4; q++) acc[f][n][q] = 0.f;

    K1_ISSUE(smb, 0);
    K1_ISSUE(smb + STAGE1, 32);

#pragma unroll 1
    for (int c = 0; c < NC1; c++) {
        if (c + 2 < NC1) { CP_WAIT1(); } else { CP_WAIT0(); }
        __syncthreads();
        if (c + 2 < NC1)
            K1_ISSUE(smb + (uint32_t)((c + 2) % 3) * STAGE1, (c + 2) * 32);
        const uint32_t sb = smb + (uint32_t)(c % 3) * STAGE1;
#pragma unroll
        for (int s = 0; s < 2; s++) {
            const uint32_t ab = sb + (uint32_t)((R + laneRow) * ROWB + laneK + 32 * s);
            uint32_t a[4][4];
#pragma unroll
            for (int f = 0; f < 4; f++)
                ldsm4(ab + (uint32_t)(16 * f * ROWB), a[f]);
#pragma unroll
            for (int gp = 0; gp < 4; gp++) {
                const uint32_t bb = sb + (uint32_t)(bSec +
                    (Cw + 16 * gp + laneRow) * ROWB + laneK + 32 * s);
                uint32_t b[4];
                ldsm4(bb, b);
#pragma unroll
                for (int f = 0; f < 4; f++)
#pragma unroll
                    for (int h = 0; h < 2; h++)
                        hmma(acc[f][2 * gp + h], a[f], b[h], b[2 + h]);
            }
        }
        __syncthreads();
    }
#undef K1_ISSUE

    // ---- epilogue: two 32-row phases; up warps park, gate warps combine ----
    float* upbuf = reinterpret_cast<float*>(sm);   // 4 x (32 x 68) floats
#pragma unroll 1
    for (int half = 0; half < 2; half++) {
        __syncthreads();
        if (wid >= 4) {
            float* base = upbuf + (wid - 4) * 2176;
#pragma unroll
            for (int fi = 0; fi < 2; fi++)
#pragma unroll
                for (int n = 0; n < 8; n++) {
                    const float* a = acc[2 * half + fi][n];
                    int row = 16 * fi + (lane >> 2);
                    int col = 8 * n + (lane & 3) * 2;
                    float* b0 = base + row * 68 + col;
                    b0[0] = a[0]; b0[1] = a[1];
                    float* b1 = b0 + 8 * 68;
                    b1[0] = a[2]; b1[1] = a[3];
                }
        }
        __syncthreads();
        if (wid < 4) {
            const float* base = upbuf + wid * 2176;
#pragma unroll
            for (int fi = 0; fi < 2; fi++)
#pragma unroll
                for (int n = 0; n < 8; n++) {
                    const float* a = acc[2 * half + fi][n];
                    int row = 16 * fi + (lane >> 2);
                    int col = 8 * n + (lane & 3) * 2;
                    const float* b0 = base + row * 68 + col;
                    const float* b1 = b0 + 8 * 68;
                    int grow = m0 + R + 32 * half + row;
                    __half* o0 = g_hh + (size_t)grow * IDIM + n0 + Cw + col;
                    __half* o1 = o0 + (size_t)8 * IDIM;
                    __half2 v0 = __floats2half2_rn(silu(a[0]) * b0[0],
                                                   silu(a[1]) * b0[1]);
                    __half2 v1 = __floats2half2_rn(silu(a[2]) * b1[0],
                                                   silu(a[3]) * b1[1]);
                    *reinterpret_cast<__half2*>(o0) = v0;
                    *reinterpret_cast<__half2*>(o1) = v1;
                }
        }
    }
}

// ---------------------------------------------------------------------------
// Kernel 2: down projection. CTA 256m x 128n, 8 warps 4m x 2n of 64x64.
// cp.async 3-stage pipeline; pure fp16 MMA.
// ---------------------------------------------------------------------------
__global__ __launch_bounds__(256, 1)
void k2_down()
{
    extern __shared__ __align__(128) char sm[];
    const uint32_t smb = smem_u32(sm);
    const int tid  = threadIdx.x;
    const int wid  = tid >> 5;
    const int lane = tid & 31;
    const int m0 = blockIdx.x * 256;   // m fastest -> Wd stays L2-resident
    const int n0 = blockIdx.y * 128;

    // cp.async geometry: A 1 thread/row (256 rows), 4x16B; B 2 thr/row, 2x16B
    const size_t aOff = (size_t)(m0 + tid) * IDIM;
    const uint32_t stA = (uint32_t)(tid * ROWB);
    const int brow = tid >> 1;
    const int bh   = tid & 1;
    const size_t bOff = (size_t)(n0 + brow) * IDIM + bh * 16;
    const uint32_t stB = (uint32_t)(brow * ROWB + bh * 32);

#define K2_ISSUE(SB, K0) do {                                                  \
    CP16((SB) + stA,             g_hh  + aOff + (K0));                         \
    CP16((SB) + stA + 16,        g_hh  + aOff + (K0) + 8);                     \
    CP16((SB) + stA + 32,        g_hh  + aOff + (K0) + 16);                    \
    CP16((SB) + stA + 48,        g_hh  + aOff + (K0) + 24);                    \
    CP16((SB) + K2_B + stB,      g_wdh + bOff + (K0));                         \
    CP16((SB) + K2_B + stB + 16, g_wdh + bOff + (K0) + 8);                     \
    CP_COMMIT();                                                               \
} while (0)

    const int laneRow = ((lane >> 3) & 1) * 8 + (lane & 7);
    const int laneK   = (lane >> 4) * 16;
    const int R   = 64 * (wid & 3);
    const int Cw  = 64 * (wid >> 2);

    float acc[4][8][4];
#pragma unroll
    for (int f = 0; f < 4; f++)
#pragma unroll
        for (int n = 0; n < 8; n++)
#pragma unroll
            for (int q = 0; q < 4; q++) acc[f][n][q] = 0.f;

    K2_ISSUE(smb, 0);
    K2_ISSUE(smb + STAGE2, 32);

#pragma unroll 1
    for (int c = 0; c < NC2; c++) {
        if (c + 2 < NC2) { CP_WAIT1(); } else { CP_WAIT0(); }
        __syncthreads();
        if (c + 2 < NC2)
            K2_ISSUE(smb + (uint32_t)((c + 2) % 3) * STAGE2, (c + 2) * 32);
        const uint32_t sb = smb + (uint32_t)(c % 3) * STAGE2;
#pragma unroll
        for (int s = 0; s < 2; s++) {
            const uint32_t ab = sb + (uint32_t)((R + laneRow) * ROWB + laneK + 32 * s);
            uint32_t a[4][4];
#pragma unroll
            for (int f = 0; f < 4; f++)
                ldsm4(ab + (uint32_t)(16 * f * ROWB), a[f]);
#pragma unroll
            for (int gp = 0; gp < 4; gp++) {
                const uint32_t bb = sb + (uint32_t)(K2_B +
                    (Cw + 16 * gp + laneRow) * ROWB + laneK + 32 * s);
                uint32_t b[4];
                ldsm4(bb, b);
#pragma unroll
                for (int f = 0; f < 4; f++)
#pragma unroll
                    for (int h = 0; h < 2; h++)
                        hmma(acc[f][2 * gp + h], a[f], b[h], b[2 + h]);
            }
        }
        __syncthreads();
    }
#undef K2_ISSUE

    // epilogue: direct fp32 stores
#pragma unroll
    for (int f = 0; f < 4; f++)
#pragma unroll
        for (int n = 0; n < 8; n++) {
            int row = m0 + R + 16 * f + (lane >> 2);
            int col = n0 + Cw + 8 * n + (lane & 3) * 2;
            float* o0 = g_down + (size_t)row * HDIM + col;
            float* o1 = o0 + (size_t)8 * HDIM;
            *reinterpret_cast<float2*>(o0) = make_float2(acc[f][n][0], acc[f][n][1]);
            *reinterpret_cast<float2*>(o1) = make_float2(acc[f][n][2], acc[f][n][3]);
        }
}

// ---------------------------------------------------------------------------
// Kernel 3: scatter
// ---------------------------------------------------------------------------
__global__ __launch_bounds__(256)
void scatter_kernel(const int* __restrict__ scatter_indices,
                    float* __restrict__ out)
{
    const int t = blockIdx.x;
    const int c = scatter_indices[t];
    const float4* src = reinterpret_cast<const float4*>(g_down + (size_t)c * HDIM);
    float4*       dst = reinterpret_cast<float4*>(out + (size_t)t * HDIM);
#pragma unroll
    for (int j = threadIdx.x; j < HDIM / 4; j += 256)
        dst[j] = src[j];
}

// ---------------------------------------------------------------------------
extern "C" void kernel_launch(void* const* d_in, const int* in_sizes, int n_in,
                              void* d_out, int out_size)
{
    const float* x  = (const float*)d_in[0];
    const float* Wg = (const float*)d_in[1];
    const float* Wu = (const float*)d_in[2];
    const float* Wd = (const float*)d_in[3];
    const int*   fg = (const int*)d_in[4];
    const int*   sc = (const int*)d_in[5];
    float*       out = (float*)d_out;

    cudaFuncSetAttribute(k1_gateup, cudaFuncAttributeMaxDynamicSharedMemorySize, SMEM1);
    cudaFuncSetAttribute(k2_down,   cudaFuncAttributeMaxDynamicSharedMemorySize, SMEM2);

    __half *wgh, *wuh, *wdh;
    cudaGetSymbolAddress((void**)&wgh, g_wgh);
    cudaGetSymbolAddress((void**)&wuh, g_wuh);
    cudaGetSymbolAddress((void**)&wdh, g_wdh);

    const int n8 = (IDIM * HDIM) / 8;   // 2M per weight
    conv_h<<<4096, 256>>>((const float4*)Wg, wgh, n8);
    conv_h<<<4096, 256>>>((const float4*)Wu, wuh, n8);
    conv_h<<<4096, 256>>>((const float4*)Wd, wdh, n8);
    conv_gather_h<<<CDIM, 256>>>(x, fg);

    dim3 g1(CDIM / 128, IDIM / 128);   // (64 m fastest, 64 n)
    k1_gateup<<<g1, 256, SMEM1>>>();

    dim3 g2(CDIM / 256, HDIM / 128);   // (32 m fastest, 16 n)
    k2_down<<<g2, 256, SMEM2>>>();

    scatter_kernel<<<NTOK, 256>>>(sc, out);
}

// round 17
// speedup vs baseline: 2.9343x; 2.9343x over previous
#include <cuda_runtime.h>
#include <cuda_fp16.h>
#include <math.h>
#include <stdint.h>

#define NTOK 16384
#define CDIM 8192
#define HDIM 2048
#define IDIM 8192

// ---------------------------------------------------------------------------
// Scratch (__device__ globals; allocation-free rule)
// ---------------------------------------------------------------------------
__device__ __align__(256) __half g_xh[(size_t)CDIM * HDIM];    // gathered x, fp16
__device__ __align__(256) __half g_wgh[(size_t)IDIM * HDIM];
__device__ __align__(256) __half g_wuh[(size_t)IDIM * HDIM];
__device__ __align__(256) __half g_wdh[(size_t)HDIM * IDIM];
__device__ __align__(256) __half g_hh[(size_t)CDIM * IDIM];    // silu(g)*u fp16
__device__ __align__(256) float  g_down[(size_t)CDIM * HDIM];

// ---------------------------------------------------------------------------
// helpers (plain sm_80-era PTX only)
// ---------------------------------------------------------------------------
__device__ __forceinline__ uint32_t smem_u32(const void* p) {
    return (uint32_t)__cvta_generic_to_shared(p);
}
__device__ __forceinline__ void ldsm4(uint32_t a, uint32_t* r) {
    asm volatile("ldmatrix.sync.aligned.m8n8.x4.shared.b16 {%0,%1,%2,%3}, [%4];"
                 : "=r"(r[0]), "=r"(r[1]), "=r"(r[2]), "=r"(r[3]) : "r"(a));
}
__device__ __forceinline__ void hmma(float* c, const uint32_t* a,
                                     uint32_t b0, uint32_t b1) {
    asm volatile(
        "mma.sync.aligned.m16n8k16.row.col.f32.f16.f16.f32 "
        "{%0,%1,%2,%3},{%4,%5,%6,%7},{%8,%9},{%0,%1,%2,%3};"
        : "+f"(c[0]), "+f"(c[1]), "+f"(c[2]), "+f"(c[3])
        : "r"(a[0]), "r"(a[1]), "r"(a[2]), "r"(a[3]), "r"(b0), "r"(b1));
}
#define CP16(dst, src) \
    asm volatile("cp.async.cg.shared.global [%0], [%1], 16;" \
                 :: "r"(dst), "l"(src))
#define CP_COMMIT() asm volatile("cp.async.commit_group;")
#define CP_WAIT1()  asm volatile("cp.async.wait_group 1;")
#define CP_WAIT0()  asm volatile("cp.async.wait_group 0;")

__device__ __forceinline__ uint2 cvt4h(float4 v) {
    __half2 a = __floats2half2_rn(v.x, v.y);
    __half2 b = __floats2half2_rn(v.z, v.w);
    return make_uint2(*reinterpret_cast<uint32_t*>(&a),
                      *reinterpret_cast<uint32_t*>(&b));
}
__device__ __forceinline__ float silu(float g) { return g / (1.f + __expf(-g)); }

// smem rows: 32 fp16 padded to 40 (80B = 5x16B) — conflict-free ldmatrix
#define ROWB 80
// k1 planes: A(128r) | G(128r) | U(128r); 3 stages
#define K1_G     10240
#define K1_U     20480
#define STAGE1   30720
#define SMEM1    (3 * STAGE1)   // 90 KB
// k2 planes: A(256r) | B(128r); 3 stages
#define K2_B     20480
#define STAGE2   30720
#define SMEM2    (3 * STAGE2)   // 90 KB

#define NC1 (HDIM / 32)   // 64 chunks
#define NC2 (IDIM / 32)   // 256 chunks

// ---------------------------------------------------------------------------
// pre-passes: fp32 -> fp16 (weights; gathered x)
// ---------------------------------------------------------------------------
__global__ __launch_bounds__(256)
void conv_h(const float4* __restrict__ W, __half* __restrict__ out, int n8)
{
    for (int i = blockIdx.x * 256 + threadIdx.x; i < n8; i += gridDim.x * 256) {
        float4 v0 = W[2 * i];
        float4 v1 = W[2 * i + 1];
        uint2 h0 = cvt4h(v0);
        uint2 h1 = cvt4h(v1);
        *reinterpret_cast<uint4*>(out + 8 * (size_t)i) =
            make_uint4(h0.x, h0.y, h1.x, h1.y);
    }
}
__global__ __launch_bounds__(256)
void conv_gather_h(const float* __restrict__ x, const int* __restrict__ fg)
{
    const int c = blockIdx.x;
    const float4* src = reinterpret_cast<const float4*>(
        x + (size_t)__ldg(fg + c) * HDIM);
    const size_t o = (size_t)c * HDIM;
#pragma unroll
    for (int i = threadIdx.x; i < HDIM / 4; i += 256)
        *reinterpret_cast<uint2*>(g_xh + o + 4 * i) = cvt4h(src[i]);
}

// ---------------------------------------------------------------------------
// Kernel 1: dual GEMM (gate,up) + SiLU. CTA 128m x 128n (both mats).
// 8 warps of 64x64: warps 0-3 gate (2m x 2n), warps 4-7 up.
// cp.async 3-stage pipeline; pure fp16 MMA. Epilogue FULLY UNROLLED
// (constant acc indices -> acc stays in registers).
// ---------------------------------------------------------------------------
__global__ __launch_bounds__(256, 1)
void k1_gateup()
{
    extern __shared__ __align__(128) char sm[];
    const uint32_t smb = smem_u32(sm);
    const int tid  = threadIdx.x;
    const int wid  = tid >> 5;
    const int lane = tid & 31;
    const int m0 = blockIdx.x * 128;   // m fastest -> B tiles L2-resident
    const int n0 = blockIdx.y * 128;

    // cp.async geometry: 2 threads/row (128 rows), 2x16B per plane per thread
    const int prow = tid >> 1;
    const int ph   = tid & 1;
    const size_t aOff = (size_t)(m0 + prow) * HDIM + ph * 16;
    const size_t bOff = (size_t)(n0 + prow) * HDIM + ph * 16;
    const uint32_t st0 = (uint32_t)(prow * ROWB + ph * 32);

#define K1_ISSUE(SB, K0) do {                                                  \
    CP16((SB) + st0,               g_xh  + aOff + (K0));                       \
    CP16((SB) + st0 + 16,          g_xh  + aOff + (K0) + 8);                   \
    CP16((SB) + K1_G + st0,        g_wgh + bOff + (K0));                       \
    CP16((SB) + K1_G + st0 + 16,   g_wgh + bOff + (K0) + 8);                   \
    CP16((SB) + K1_U + st0,        g_wuh + bOff + (K0));                       \
    CP16((SB) + K1_U + st0 + 16,   g_wuh + bOff + (K0) + 8);                   \
    CP_COMMIT();                                                               \
} while (0)

    // ldmatrix lane geometry; warp tile 64x64
    const int laneRow = ((lane >> 3) & 1) * 8 + (lane & 7);
    const int laneK   = (lane >> 4) * 16;
    const int wg  = wid & 3;
    const int R   = 64 * (wg >> 1);
    const int Cw  = 64 * (wg & 1);
    const int bSec = (wid >= 4) ? K1_U : K1_G;

    float acc[4][8][4];
#pragma unroll
    for (int f = 0; f < 4; f++)
#pragma unroll
        for (int n = 0; n < 8; n++)
#pragma unroll
            for (int q = 0; q < 4; q++) acc[f][n][q] = 0.f;

    K1_ISSUE(smb, 0);
    K1_ISSUE(smb + STAGE1, 32);

#pragma unroll 1
    for (int c = 0; c < NC1; c++) {
        if (c + 2 < NC1) { CP_WAIT1(); } else { CP_WAIT0(); }
        __syncthreads();
        if (c + 2 < NC1)
            K1_ISSUE(smb + (uint32_t)((c + 2) % 3) * STAGE1, (c + 2) * 32);
        const uint32_t sb = smb + (uint32_t)(c % 3) * STAGE1;
#pragma unroll
        for (int s = 0; s < 2; s++) {
            const uint32_t ab = sb + (uint32_t)((R + laneRow) * ROWB + laneK + 32 * s);
            uint32_t a[4][4];
#pragma unroll
            for (int f = 0; f < 4; f++)
                ldsm4(ab + (uint32_t)(16 * f * ROWB), a[f]);
#pragma unroll
            for (int gp = 0; gp < 4; gp++) {
                const uint32_t bb = sb + (uint32_t)(bSec +
                    (Cw + 16 * gp + laneRow) * ROWB + laneK + 32 * s);
                uint32_t b[4];
                ldsm4(bb, b);
#pragma unroll
                for (int f = 0; f < 4; f++)
#pragma unroll
                    for (int h = 0; h < 2; h++)
                        hmma(acc[f][2 * gp + h], a[f], b[h], b[2 + h]);
            }
        }
        __syncthreads();
    }
#undef K1_ISSUE

    // ---- epilogue: two 32-row phases, FULLY UNROLLED (constant acc idx) ----
    float* upbuf = reinterpret_cast<float*>(sm);   // 4 x (32 x 68) floats
#pragma unroll
    for (int half = 0; half < 2; half++) {
        __syncthreads();
        if (wid >= 4) {
            float* base = upbuf + (wid - 4) * 2176;
#pragma unroll
            for (int fi = 0; fi < 2; fi++)
#pragma unroll
                for (int n = 0; n < 8; n++) {
                    const float* a = acc[2 * half + fi][n];
                    int row = 16 * fi + (lane >> 2);
                    int col = 8 * n + (lane & 3) * 2;
                    float* b0 = base + row * 68 + col;
                    b0[0] = a[0]; b0[1] = a[1];
                    float* b1 = b0 + 8 * 68;
                    b1[0] = a[2]; b1[1] = a[3];
                }
        }
        __syncthreads();
        if (wid < 4) {
            const float* base = upbuf + wid * 2176;
#pragma unroll
            for (int fi = 0; fi < 2; fi++)
#pragma unroll
                for (int n = 0; n < 8; n++) {
                    const float* a = acc[2 * half + fi][n];
                    int row = 16 * fi + (lane >> 2);
                    int col = 8 * n + (lane & 3) * 2;
                    const float* b0 = base + row * 68 + col;
                    const float* b1 = b0 + 8 * 68;
                    int grow = m0 + R + 32 * half + row;
                    __half* o0 = g_hh + (size_t)grow * IDIM + n0 + Cw + col;
                    __half* o1 = o0 + (size_t)8 * IDIM;
                    __half2 v0 = __floats2half2_rn(silu(a[0]) * b0[0],
                                                   silu(a[1]) * b0[1]);
                    __half2 v1 = __floats2half2_rn(silu(a[2]) * b1[0],
                                                   silu(a[3]) * b1[1]);
                    *reinterpret_cast<__half2*>(o0) = v0;
                    *reinterpret_cast<__half2*>(o1) = v1;
                }
        }
    }
}

// ---------------------------------------------------------------------------
// Kernel 2: down projection. CTA 256m x 128n, 8 warps 4m x 2n of 64x64.
// cp.async 3-stage pipeline; pure fp16 MMA. (Constant acc indices throughout.)
// ---------------------------------------------------------------------------
__global__ __launch_bounds__(256, 1)
void k2_down()
{
    extern __shared__ __align__(128) char sm[];
    const uint32_t smb = smem_u32(sm);
    const int tid  = threadIdx.x;
    const int wid  = tid >> 5;
    const int lane = tid & 31;
    const int m0 = blockIdx.x * 256;   // m fastest -> Wd stays L2-resident
    const int n0 = blockIdx.y * 128;

    const size_t aOff = (size_t)(m0 + tid) * IDIM;
    const uint32_t stA = (uint32_t)(tid * ROWB);
    const int brow = tid >> 1;
    const int bh   = tid & 1;
    const size_t bOff = (size_t)(n0 + brow) * IDIM + bh * 16;
    const uint32_t stB = (uint32_t)(brow * ROWB + bh * 32);

#define K2_ISSUE(SB, K0) do {                                                  \
    CP16((SB) + stA,             g_hh  + aOff + (K0));                         \
    CP16((SB) + stA + 16,        g_hh  + aOff + (K0) + 8);                     \
    CP16((SB) + stA + 32,        g_hh  + aOff + (K0) + 16);                    \
    CP16((SB) + stA + 48,        g_hh  + aOff + (K0) + 24);                    \
    CP16((SB) + K2_B + stB,      g_wdh + bOff + (K0));                         \
    CP16((SB) + K2_B + stB + 16, g_wdh + bOff + (K0) + 8);                     \
    CP_COMMIT();                                                               \
} while (0)

    const int laneRow = ((lane >> 3) & 1) * 8 + (lane & 7);
    const int laneK   = (lane >> 4) * 16;
    const int R   = 64 * (wid & 3);
    const int Cw  = 64 * (wid >> 2);

    float acc[4][8][4];
#pragma unroll
    for (int f = 0; f < 4; f++)
#pragma unroll
        for (int n = 0; n < 8; n++)
#pragma unroll
            for (int q = 0; q < 4; q++) acc[f][n][q] = 0.f;

    K2_ISSUE(smb, 0);
    K2_ISSUE(smb + STAGE2, 32);

#pragma unroll 1
    for (int c = 0; c < NC2; c++) {
        if (c + 2 < NC2) { CP_WAIT1(); } else { CP_WAIT0(); }
        __syncthreads();
        if (c + 2 < NC2)
            K2_ISSUE(smb + (uint32_t)((c + 2) % 3) * STAGE2, (c + 2) * 32);
        const uint32_t sb = smb + (uint32_t)(c % 3) * STAGE2;
#pragma unroll
        for (int s = 0; s < 2; s++) {
            const uint32_t ab = sb + (uint32_t)((R + laneRow) * ROWB + laneK + 32 * s);
            uint32_t a[4][4];
#pragma unroll
            for (int f = 0; f < 4; f++)
                ldsm4(ab + (uint32_t)(16 * f * ROWB), a[f]);
#pragma unroll
            for (int gp = 0; gp < 4; gp++) {
                const uint32_t bb = sb + (uint32_t)(K2_B +
                    (Cw + 16 * gp + laneRow) * ROWB + laneK + 32 * s);
                uint32_t b[4];
                ldsm4(bb, b);
#pragma unroll
                for (int f = 0; f < 4; f++)
#pragma unroll
                    for (int h = 0; h < 2; h++)
                        hmma(acc[f][2 * gp + h], a[f], b[h], b[2 + h]);
            }
        }
        __syncthreads();
    }
#undef K2_ISSUE

    // epilogue: direct fp32 stores
#pragma unroll
    for (int f = 0; f < 4; f++)
#pragma unroll
        for (int n = 0; n < 8; n++) {
            int row = m0 + R + 16 * f + (lane >> 2);
            int col = n0 + Cw + 8 * n + (lane & 3) * 2;
            float* o0 = g_down + (size_t)row * HDIM + col;
            float* o1 = o0 + (size_t)8 * HDIM;
            *reinterpret_cast<float2*>(o0) = make_float2(acc[f][n][0], acc[f][n][1]);
            *reinterpret_cast<float2*>(o1) = make_float2(acc[f][n][2], acc[f][n][3]);
        }
}

// ---------------------------------------------------------------------------
// Kernel 3: scatter
// ---------------------------------------------------------------------------
__global__ __launch_bounds__(256)
void scatter_kernel(const int* __restrict__ scatter_indices,
                    float* __restrict__ out)
{
    const int t = blockIdx.x;
    const int c = scatter_indices[t];
    const float4* src = reinterpret_cast<const float4*>(g_down + (size_t)c * HDIM);
    float4*       dst = reinterpret_cast<float4*>(out + (size_t)t * HDIM);
#pragma unroll
    for (int j = threadIdx.x; j < HDIM / 4; j += 256)
        dst[j] = src[j];
}

// ---------------------------------------------------------------------------
extern "C" void kernel_launch(void* const* d_in, const int* in_sizes, int n_in,
                              void* d_out, int out_size)
{
    const float* x  = (const float*)d_in[0];
    const float* Wg = (const float*)d_in[1];
    const float* Wu = (const float*)d_in[2];
    const float* Wd = (const float*)d_in[3];
    const int*   fg = (const int*)d_in[4];
    const int*   sc = (const int*)d_in[5];
    float*       out = (float*)d_out;

    cudaFuncSetAttribute(k1_gateup, cudaFuncAttributeMaxDynamicSharedMemorySize, SMEM1);
    cudaFuncSetAttribute(k2_down,   cudaFuncAttributeMaxDynamicSharedMemorySize, SMEM2);

    __half *wgh, *wuh, *wdh;
    cudaGetSymbolAddress((void**)&wgh, g_wgh);
    cudaGetSymbolAddress((void**)&wuh, g_wuh);
    cudaGetSymbolAddress((void**)&wdh, g_wdh);

    const int n8 = (IDIM * HDIM) / 8;   // 2M per weight
    conv_h<<<4096, 256>>>((const float4*)Wg, wgh, n8);
    conv_h<<<4096, 256>>>((const float4*)Wu, wuh, n8);
    conv_h<<<4096, 256>>>((const float4*)Wd, wdh, n8);
    conv_gather_h<<<CDIM, 256>>>(x, fg);

    dim3 g1(CDIM / 128, IDIM / 128);   // (64 m fastest, 64 n)
    k1_gateup<<<g1, 256, SMEM1>>>();

    dim3 g2(CDIM / 256, HDIM / 128);   // (32 m fastest, 16 n)
    k2_down<<<g2, 256, SMEM2>>>();

    scatter_kernel<<<NTOK, 256>>>(sc, out);
}